// round 2
// baseline (speedup 1.0000x reference)
#include <cuda_runtime.h>
#include <math.h>

// Problem constants (fixed by the reference build)
#define MM   4096      // checks
#define NN   8192      // variables
#define BB   256       // batch
#define EE   32768     // edges  (NN * DV)
#define N_ITERS 10
#define ALPHA_C 0.8f
#define CLAMP_V 20.0f
#define PAD_BIG_C 1.0e6f

// ---------------- static device scratch (no allocations allowed) -----------
__device__ float g_ctv  [EE * BB];   // check->var messages, edge-major [E,B]
__device__ float g_vt   [NN * BB];   // per-var sum of incoming ctv, [N,B]
__device__ float g_llr_t[NN * BB];   // transposed channel LLR, [N,B]
__device__ float g_ssign[MM * BB];   // 1-2*syndrome, [M,B]
__device__ float g_marg [NN * BB];   // marginals, [N,B]
__device__ float g_hard [NN * BB];   // hard decisions (0/1 float), [N,B]

// ---------------- kernels ---------------------------------------------------
// NOTE: device globals are only referenced from DEVICE code (never passed as
// kernel arguments from host — the host-side symbol shadow is not a device
// pointer; that was the R1 bug).

// Transpose INPUT [rows, cols] (row-major, device pointer) into a device
// global laid out [cols, rows].  DST: 0 -> g_llr_t, 1 -> g_ssign (with 1-2x).
template<int DST>
__global__ void k_tr_in(const float* __restrict__ in, int rows, int cols)
{
    float* out = (DST == 0) ? g_llr_t : g_ssign;
    __shared__ float tile[32][33];
    int c0 = blockIdx.x * 32;
    int r0 = blockIdx.y * 32;
    int c = c0 + threadIdx.x;
    #pragma unroll
    for (int i = 0; i < 32; i += 8) {
        int r = r0 + threadIdx.y + i;
        if (r < rows && c < cols)
            tile[threadIdx.y + i][threadIdx.x] = in[(size_t)r * cols + c];
    }
    __syncthreads();
    int oc = r0 + threadIdx.x;            // output column (= input row)
    #pragma unroll
    for (int i = 0; i < 32; i += 8) {
        int orow = c0 + threadIdx.y + i;  // output row (= input col)
        if (orow < cols && oc < rows) {
            float v = tile[threadIdx.x][threadIdx.y + i];
            if (DST == 1) v = 1.0f - 2.0f * v;
            out[(size_t)orow * rows + oc] = v;
        }
    }
}

// Transpose a device-global [rows, cols] into OUTPUT (device pointer, d_out).
// SRC: 0 -> g_marg, 1 -> g_hard.
template<int SRC>
__global__ void k_tr_out(float* __restrict__ out, int rows, int cols)
{
    const float* in = (SRC == 0) ? g_marg : g_hard;
    __shared__ float tile[32][33];
    int c0 = blockIdx.x * 32;
    int r0 = blockIdx.y * 32;
    int c = c0 + threadIdx.x;
    #pragma unroll
    for (int i = 0; i < 32; i += 8) {
        int r = r0 + threadIdx.y + i;
        if (r < rows && c < cols)
            tile[threadIdx.y + i][threadIdx.x] = in[(size_t)r * cols + c];
    }
    __syncthreads();
    int oc = r0 + threadIdx.x;
    #pragma unroll
    for (int i = 0; i < 32; i += 8) {
        int orow = c0 + threadIdx.y + i;
        if (orow < cols && oc < rows)
            out[(size_t)orow * rows + oc] = tile[threadIdx.x][threadIdx.y + i];
    }
}

__global__ void k_zero_ctv()
{
    size_t n = (size_t)EE * BB;
    for (size_t i = (size_t)blockIdx.x * blockDim.x + threadIdx.x; i < n;
         i += (size_t)gridDim.x * blockDim.x)
        g_ctv[i] = 0.0f;
}

// Kernel A: per-variable sum of the 4 incoming ctv messages
__global__ void k_varsum(const int* __restrict__ var_adj)
{
    int v = blockIdx.x;
    int b = threadIdx.x;
    int4 e = __ldg((const int4*)var_adj + v);   // exactly DV=4 edges per var
    float s = g_ctv[(size_t)e.x * BB + b]
            + g_ctv[(size_t)e.y * BB + b]
            + g_ctv[(size_t)e.z * BB + b]
            + g_ctv[(size_t)e.w * BB + b];
    g_vt[(size_t)v * BB + b] = s;
}

// Kernel B: min-sum check update. One block per check, thread = batch index.
// Shared mem caches the clamped v->c messages for the exclusion pass.
// The reference pads check_adj with edge 0, so min1/min2 are seeded with
// |vtc[edge 0]| + 1e6 (exact replication, matters only for degree<=1 checks).
__global__ void k_checkupd(const int* __restrict__ check_adj,
                           const float* __restrict__ check_mask,
                           const int* __restrict__ var_idx,
                           int max_dc)
{
    extern __shared__ float sx[];           // [max_dc][BB]
    int c = blockIdx.x;
    int b = threadIdx.x;
    const int*   adj = check_adj  + (size_t)c * max_dc;
    const float* msk = check_mask + (size_t)c * max_dc;

    // pad value: vtc along global edge 0 for this batch lane
    int   v0  = __ldg(var_idx);             // var of edge 0
    float x0  = g_llr_t[(size_t)v0 * BB + b]
              + g_vt   [(size_t)v0 * BB + b]
              - g_ctv  [b];
    x0 = fminf(fmaxf(x0, -CLAMP_V), CLAMP_V);
    float pad = fabsf(x0) + PAD_BIG_C;

    float sgn = g_ssign[(size_t)c * BB + b];   // accumulates s_sign * prod(signs)
    float m1 = pad, m2 = pad;

    for (int j = 0; j < max_dc; j++) {
        if (__ldg(msk + j) != 0.0f) {
            int e = __ldg(adj + j);
            int v = __ldg(var_idx + e);
            float x = g_llr_t[(size_t)v * BB + b]
                    + g_vt   [(size_t)v * BB + b]
                    - g_ctv  [(size_t)e * BB + b];
            x = fminf(fmaxf(x, -CLAMP_V), CLAMP_V);
            sx[j * BB + b] = x;
            if (x < 0.0f) sgn = -sgn;          // sign(0) = +1, matches vg>=0 rule
            float a = fabsf(x);
            if (a < m1) { m2 = m1; m1 = a; }
            else if (a < m2) { m2 = a; }
        }
    }
    for (int j = 0; j < max_dc; j++) {
        if (__ldg(msk + j) != 0.0f) {
            int e = __ldg(adj + j);
            float x  = sx[j * BB + b];
            float se = (x < 0.0f) ? -1.0f : 1.0f;
            float a  = fabsf(x);
            float m  = (fabsf(a - m1) < 1e-9f) ? m2 : m1;
            g_ctv[(size_t)e * BB + b] = ALPHA_C * sgn * se * m;
        }
    }
}

// marginals + hard decisions (v-major)
__global__ void k_finalize()
{
    int v = blockIdx.x;
    int b = threadIdx.x;
    size_t i = (size_t)v * BB + b;
    float t = g_llr_t[i] + g_vt[i];
    float marg = 1.0f / (1.0f + expf(t));     // sigmoid(-t)
    g_marg[i] = marg;
    g_hard[i] = (marg > 0.5f) ? 1.0f : 0.0f;
}

__global__ void k_initconv(float* __restrict__ conv)
{
    conv[threadIdx.x] = 1.0f;
}

// Parity check per (check, batch): if mismatch, converged[b] = 0
__global__ void k_parity(const int* __restrict__ check_adj,
                         const float* __restrict__ check_mask,
                         const int* __restrict__ var_idx,
                         int max_dc, float* __restrict__ conv)
{
    int c = blockIdx.x;
    int b = threadIdx.x;
    const int*   adj = check_adj  + (size_t)c * max_dc;
    const float* msk = check_mask + (size_t)c * max_dc;
    int p = 0;
    for (int j = 0; j < max_dc; j++) {
        if (__ldg(msk + j) != 0.0f) {
            int e = __ldg(adj + j);
            int v = __ldg(var_idx + e);
            p += (int)g_hard[(size_t)v * BB + b];
        }
    }
    int s = (g_ssign[(size_t)c * BB + b] < 0.0f) ? 1 : 0;
    if ((p & 1) != s) conv[b] = 0.0f;        // benign race: everyone writes 0
}

// ---------------- launch ----------------------------------------------------

extern "C" void kernel_launch(void* const* d_in, const int* in_sizes, int n_in,
                              void* d_out, int out_size)
{
    const float* syndrome   = (const float*)d_in[0];   // [B, M]
    const float* llr        = (const float*)d_in[1];   // [B, N]
    const int*   var_adj    = (const int*)  d_in[2];   // [N, 4]
    // d_in[3] var_adj_mask: all ones (DV regular) — unused
    const int*   check_adj  = (const int*)  d_in[4];   // [M, max_dc]
    const float* check_mask = (const float*)d_in[5];   // [M, max_dc]
    const int*   var_idx    = (const int*)  d_in[6];   // [E]
    // d_in[7] pcm_dense — unused (parity computed from adjacency)

    const int max_dc = in_sizes[4] / MM;
    float* out = (float*)d_out;
    size_t bn = (size_t)BB * NN;
    float* out_marg = out;            // [B, N]
    float* out_hard = out + bn;       // [B, N]
    float* out_conv = out + 2 * bn;   // [B]

    size_t smem = (size_t)max_dc * BB * sizeof(float);
    if (smem > 48 * 1024) {
        cudaFuncSetAttribute(k_checkupd, cudaFuncAttributeMaxDynamicSharedMemorySize,
                             (int)smem);
    }

    dim3 tb(32, 8);
    // llr [B,N] -> g_llr_t [N,B]
    k_tr_in<0><<<dim3(NN / 32, BB / 32), tb>>>(llr, BB, NN);
    // syndrome [B,M] -> g_ssign [M,B] with 1-2x
    k_tr_in<1><<<dim3(MM / 32, BB / 32), tb>>>(syndrome, BB, MM);

    k_zero_ctv<<<4096, 256>>>();

    for (int it = 0; it < N_ITERS; it++) {
        k_varsum  <<<NN, BB>>>(var_adj);
        k_checkupd<<<MM, BB, smem>>>(check_adj, check_mask, var_idx, max_dc);
    }
    k_varsum<<<NN, BB>>>(var_adj);
    k_finalize<<<NN, BB>>>();

    // g_marg [N,B] -> out_marg [B,N] ; g_hard [N,B] -> out_hard [B,N]
    k_tr_out<0><<<dim3(BB / 32, NN / 32), tb>>>(out_marg, NN, BB);
    k_tr_out<1><<<dim3(BB / 32, NN / 32), tb>>>(out_hard, NN, BB);

    k_initconv<<<1, BB>>>(out_conv);
    k_parity<<<MM, BB>>>(check_adj, check_mask, var_idx, max_dc, out_conv);
}

// round 3
// speedup vs baseline: 1.5602x; 1.5602x over previous
#include <cuda_runtime.h>
#include <math.h>

// Problem constants (fixed by the reference build)
#define MM   4096      // checks
#define NN   8192      // variables
#define BB   256       // batch
#define EE   32768     // edges  (NN * DV)
#define N_ITERS 10
#define ALPHA_C 0.8f
#define CLAMP_V 20.0f
#define PAD_BIG_C 1.0e6f

// ---------------- static device scratch (no allocations allowed) -----------
__device__ float g_ctv  [EE * BB];   // check->var messages, edge-major [E,B]
__device__ float g_vext [NN * BB];   // llr + sum of incoming ctv, [N,B]
__device__ float g_llr_t[NN * BB];   // transposed channel LLR, [N,B]
__device__ float g_ssign[MM * BB];   // 1-2*syndrome, [M,B]
__device__ float g_hard [NN * BB];   // hard decisions, [N,B] (for parity)
__device__ int   g_deg  [MM];        // check degrees

// ---------------- helpers ----------------------------------------------------
__device__ __forceinline__ float clampv(float x) {
    return fminf(fmaxf(x, -CLAMP_V), CLAMP_V);
}

// ---------------- kernels ---------------------------------------------------
// Device globals referenced only from device code.

// Transpose INPUT [rows, cols] into device global [cols, rows].
// DST: 0 -> g_llr_t AND g_vext (iter-0 vext == llr), 1 -> g_ssign (1-2x).
template<int DST>
__global__ void k_tr_in(const float* __restrict__ in, int rows, int cols)
{
    __shared__ float tile[32][33];
    int c0 = blockIdx.x * 32;
    int r0 = blockIdx.y * 32;
    int c = c0 + threadIdx.x;
    #pragma unroll
    for (int i = 0; i < 32; i += 8) {
        int r = r0 + threadIdx.y + i;
        tile[threadIdx.y + i][threadIdx.x] = in[(size_t)r * cols + c];
    }
    __syncthreads();
    int oc = r0 + threadIdx.x;            // output column (= input row)
    #pragma unroll
    for (int i = 0; i < 32; i += 8) {
        int orow = c0 + threadIdx.y + i;  // output row (= input col)
        size_t oi = (size_t)orow * rows + oc;
        float v = tile[threadIdx.x][threadIdx.y + i];
        if (DST == 0) { g_llr_t[oi] = v; g_vext[oi] = v; }
        else          { g_ssign[oi] = 1.0f - 2.0f * v; }
    }
}

// Per-check degree from the mask (prefix property holds by construction).
__global__ void k_deg(const float* __restrict__ check_mask, int max_dc)
{
    int c = blockIdx.x * blockDim.x + threadIdx.x;
    if (c >= MM) return;
    const float* m = check_mask + (size_t)c * max_dc;
    int d = 0;
    for (int j = 0; j < max_dc; j++) d += (__ldg(m + j) != 0.0f);
    g_deg[c] = d;
}

// Var side: vext[v] = llr[v] + sum of 4 incoming ctv. float4 over batch.
// Block = 256 threads = 4 vars x 64 float4-lanes.
__global__ void k_varsum(const int* __restrict__ var_adj)
{
    int t = threadIdx.x;
    int v = blockIdx.x * 4 + (t >> 6);
    int j = t & 63;
    int4 e = __ldg((const int4*)var_adj + v);
    float4 a = ((const float4*)(g_ctv + (size_t)e.x * BB))[j];
    float4 b = ((const float4*)(g_ctv + (size_t)e.y * BB))[j];
    float4 c = ((const float4*)(g_ctv + (size_t)e.z * BB))[j];
    float4 d = ((const float4*)(g_ctv + (size_t)e.w * BB))[j];
    float4 l = ((const float4*)(g_llr_t + (size_t)v * BB))[j];
    float4 s;
    s.x = l.x + a.x + b.x + c.x + d.x;
    s.y = l.y + a.y + b.y + c.y + d.y;
    s.z = l.z + a.z + b.z + c.z + d.z;
    s.w = l.w + a.w + b.w + c.w + d.w;
    ((float4*)(g_vext + (size_t)v * BB))[j] = s;
}

// Check side: min-sum update. Block = 256 threads = 4 checks x 64 float4-lanes.
// FIRST: ctv==0 (iteration 0), skip ctv reads.
template<bool FIRST>
__global__ void k_checkupd(const int* __restrict__ check_adj,
                           const int* __restrict__ var_idx,
                           int max_dc)
{
    int t = threadIdx.x;
    int c = blockIdx.x * 4 + (t >> 6);
    int j = t & 63;
    int deg = g_deg[c];
    if (deg == 0) return;
    const int* adj = check_adj + (size_t)c * max_dc;

    float4 sg = ((const float4*)(g_ssign + (size_t)c * BB))[j];
    float4 m1, m2;
    if (deg == 1) {
        // reference pads with global edge 0: seed = |vtc(edge0)| + 1e6
        int v0 = __ldg(var_idx);
        float4 x0 = ((const float4*)(g_vext + (size_t)v0 * BB))[j];
        if (!FIRST) {
            float4 c0 = ((const float4*)g_ctv)[j];
            x0.x -= c0.x; x0.y -= c0.y; x0.z -= c0.z; x0.w -= c0.w;
        }
        m1.x = fabsf(clampv(x0.x)) + PAD_BIG_C;
        m1.y = fabsf(clampv(x0.y)) + PAD_BIG_C;
        m1.z = fabsf(clampv(x0.z)) + PAD_BIG_C;
        m1.w = fabsf(clampv(x0.w)) + PAD_BIG_C;
    } else {
        m1.x = m1.y = m1.z = m1.w = 1.0e30f;   // pad can never win for deg>=2
    }
    m2 = m1;

    // pass 1: sign product + two smallest magnitudes
    for (int p = 0; p < deg; p++) {
        int e = __ldg(adj + p);
        int v = __ldg(var_idx + e);
        float4 x = ((const float4*)(g_vext + (size_t)v * BB))[j];
        if (!FIRST) {
            float4 o = ((const float4*)(g_ctv + (size_t)e * BB))[j];
            x.x -= o.x; x.y -= o.y; x.z -= o.z; x.w -= o.w;
        }
        x.x = clampv(x.x); x.y = clampv(x.y); x.z = clampv(x.z); x.w = clampv(x.w);
        if (x.x < 0.0f) sg.x = -sg.x;
        if (x.y < 0.0f) sg.y = -sg.y;
        if (x.z < 0.0f) sg.z = -sg.z;
        if (x.w < 0.0f) sg.w = -sg.w;
        float a;
        a = fabsf(x.x); if (a < m1.x) { m2.x = m1.x; m1.x = a; } else if (a < m2.x) m2.x = a;
        a = fabsf(x.y); if (a < m1.y) { m2.y = m1.y; m1.y = a; } else if (a < m2.y) m2.y = a;
        a = fabsf(x.z); if (a < m1.z) { m2.z = m1.z; m1.z = a; } else if (a < m2.z) m2.z = a;
        a = fabsf(x.w); if (a < m1.w) { m2.w = m1.w; m1.w = a; } else if (a < m2.w) m2.w = a;
    }

    // pass 2: recompute x (L1-warm), write new messages
    for (int p = 0; p < deg; p++) {
        int e = __ldg(adj + p);
        int v = __ldg(var_idx + e);
        float4 x = ((const float4*)(g_vext + (size_t)v * BB))[j];
        if (!FIRST) {
            float4 o = ((const float4*)(g_ctv + (size_t)e * BB))[j];
            x.x -= o.x; x.y -= o.y; x.z -= o.z; x.w -= o.w;
        }
        x.x = clampv(x.x); x.y = clampv(x.y); x.z = clampv(x.z); x.w = clampv(x.w);
        float4 out;
        {
            float a = fabsf(x.x);
            float m = (fabsf(a - m1.x) < 1e-9f) ? m2.x : m1.x;
            float se = (x.x < 0.0f) ? -1.0f : 1.0f;
            out.x = ALPHA_C * sg.x * se * m;
        }
        {
            float a = fabsf(x.y);
            float m = (fabsf(a - m1.y) < 1e-9f) ? m2.y : m1.y;
            float se = (x.y < 0.0f) ? -1.0f : 1.0f;
            out.y = ALPHA_C * sg.y * se * m;
        }
        {
            float a = fabsf(x.z);
            float m = (fabsf(a - m1.z) < 1e-9f) ? m2.z : m1.z;
            float se = (x.z < 0.0f) ? -1.0f : 1.0f;
            out.z = ALPHA_C * sg.z * se * m;
        }
        {
            float a = fabsf(x.w);
            float m = (fabsf(a - m1.w) < 1e-9f) ? m2.w : m1.w;
            float se = (x.w < 0.0f) ? -1.0f : 1.0f;
            out.w = ALPHA_C * sg.w * se * m;
        }
        ((float4*)(g_ctv + (size_t)e * BB))[j] = out;
    }
}

// Final: read g_vext (= total_llr), write marginals + hard to d_out [B,N],
// and hard to g_hard [N,B] for the parity kernel.
__global__ void k_out(float* __restrict__ out_marg, float* __restrict__ out_hard)
{
    __shared__ float tile[32][33];
    int c0 = blockIdx.x * 32;   // batch tile
    int r0 = blockIdx.y * 32;   // var tile
    int c = c0 + threadIdx.x;
    #pragma unroll
    for (int i = 0; i < 32; i += 8) {
        int r = r0 + threadIdx.y + i;
        tile[threadIdx.y + i][threadIdx.x] = g_vext[(size_t)r * BB + c];
    }
    // also produce g_hard [N,B] with coalesced writes
    #pragma unroll
    for (int i = 0; i < 32; i += 8) {
        int r = r0 + threadIdx.y + i;
        float t = tile[threadIdx.y + i][threadIdx.x];
        float marg = 1.0f / (1.0f + expf(t));
        g_hard[(size_t)r * BB + c] = (marg > 0.5f) ? 1.0f : 0.0f;
    }
    __syncthreads();
    int oc = r0 + threadIdx.x;            // var index in output
    #pragma unroll
    for (int i = 0; i < 32; i += 8) {
        int orow = c0 + threadIdx.y + i;  // batch index in output
        float t = tile[threadIdx.x][threadIdx.y + i];
        float marg = 1.0f / (1.0f + expf(t));
        size_t oi = (size_t)orow * NN + oc;
        out_marg[oi] = marg;
        out_hard[oi] = (marg > 0.5f) ? 1.0f : 0.0f;
    }
}

__global__ void k_initconv(float* __restrict__ conv)
{
    conv[threadIdx.x] = 1.0f;
}

// Parity per (check, batch-quad): mismatch -> converged[b] = 0.
__global__ void k_parity(const int* __restrict__ check_adj,
                         const int* __restrict__ var_idx,
                         int max_dc, float* __restrict__ conv)
{
    int t = threadIdx.x;
    int c = blockIdx.x * 4 + (t >> 6);
    int j = t & 63;
    int deg = g_deg[c];
    const int* adj = check_adj + (size_t)c * max_dc;
    int p0 = 0, p1 = 0, p2 = 0, p3 = 0;
    for (int p = 0; p < deg; p++) {
        int e = __ldg(adj + p);
        int v = __ldg(var_idx + e);
        float4 h = ((const float4*)(g_hard + (size_t)v * BB))[j];
        p0 += (int)h.x; p1 += (int)h.y; p2 += (int)h.z; p3 += (int)h.w;
    }
    float4 sg = ((const float4*)(g_ssign + (size_t)c * BB))[j];
    if ((p0 & 1) != (sg.x < 0.0f ? 1 : 0)) conv[j * 4 + 0] = 0.0f;
    if ((p1 & 1) != (sg.y < 0.0f ? 1 : 0)) conv[j * 4 + 1] = 0.0f;
    if ((p2 & 1) != (sg.z < 0.0f ? 1 : 0)) conv[j * 4 + 2] = 0.0f;
    if ((p3 & 1) != (sg.w < 0.0f ? 1 : 0)) conv[j * 4 + 3] = 0.0f;
}

// ---------------- launch ----------------------------------------------------

extern "C" void kernel_launch(void* const* d_in, const int* in_sizes, int n_in,
                              void* d_out, int out_size)
{
    const float* syndrome   = (const float*)d_in[0];   // [B, M]
    const float* llr        = (const float*)d_in[1];   // [B, N]
    const int*   var_adj    = (const int*)  d_in[2];   // [N, 4]
    const int*   check_adj  = (const int*)  d_in[4];   // [M, max_dc]
    const float* check_mask = (const float*)d_in[5];   // [M, max_dc]
    const int*   var_idx    = (const int*)  d_in[6];   // [E]

    const int max_dc = in_sizes[4] / MM;
    float* out = (float*)d_out;
    size_t bn = (size_t)BB * NN;
    float* out_marg = out;            // [B, N]
    float* out_hard = out + bn;       // [B, N]
    float* out_conv = out + 2 * bn;   // [B]

    dim3 tb(32, 8);
    k_tr_in<0><<<dim3(NN / 32, BB / 32), tb>>>(llr, BB, NN);      // -> llr_t + vext
    k_tr_in<1><<<dim3(MM / 32, BB / 32), tb>>>(syndrome, BB, MM); // -> ssign
    k_deg<<<(MM + 255) / 256, 256>>>(check_mask, max_dc);

    k_checkupd<true><<<MM / 4, 256>>>(check_adj, var_idx, max_dc);
    for (int it = 1; it < N_ITERS; it++) {
        k_varsum<<<NN / 4, 256>>>(var_adj);
        k_checkupd<false><<<MM / 4, 256>>>(check_adj, var_idx, max_dc);
    }
    k_varsum<<<NN / 4, 256>>>(var_adj);   // final vext = total_llr

    k_out<<<dim3(BB / 32, NN / 32), tb>>>(out_marg, out_hard);
    k_initconv<<<1, BB>>>(out_conv);
    k_parity<<<MM / 4, 256>>>(check_adj, var_idx, max_dc, out_conv);
}